// round 10
// baseline (speedup 1.0000x reference)
#include <cuda_runtime.h>

// CostVolume3D: B=8, H=128, W=256, C=8, MAX_DISP=12 -> D=23.
// tile(...,D) + raw reshape => every tiled read is orig.flat[p/23].
// Segment-sum over the <=4 constant-value runs of c=0..7, with the segment
// structure (lengths + cumulative-flip coefficients) precomputed into a
// compile-time LUT indexed by (rL, r0, e) — 1058 entries x 48B, L1-resident.
// Runtime per segment: e_k = e0 + a*dA + b*D0 + c*D1; acc += len*|e_k|.
// 4 outputs per thread (quad), float4 store.

#define B_ 8
#define H_ 128
#define W_ 256
#define D_ 23

static constexpr int TOTAL = B_ * H_ * W_ * D_;   // 6,029,312 (div by 4)
static constexpr int NF    = B_ * H_ * W_ * 8;    // 2,097,152
static constexpr int NW    = B_ * H_ * W_;        // 262,144

// LUT entry layout (3 x float4):
//   v[0..3]  = (a1, b1, c1, len1)   segment 1 coeffs + length
//   v[4..7]  = (a2, b2, c2, len2)   segment 2 coeffs + length
//   v[8..11] = (len0, len3, 0, 0)   segment 0/3 lengths (seg3 coeffs == 1)
struct alignas(16) LutEntry { float v[12]; };
struct LutAll { LutEntry e[23 * 23 * 2]; };

constexpr LutAll gen_lut() {
    LutAll L{};
    for (int rL = 0; rL < 23; rL++)
        for (int r0 = 0; r0 < 23; r0++)
            for (int e = 0; e < 2; e++) {
                const int r1 = e ? (r0 + 8) % 23 : r0;
                int tL = 23 - rL; if (tL > 8) tL = 8;   // stream flips at c = t
                int t0 = 23 - r0; if (t0 > 8) t0 = 8;
                int t1 = 23 - r1; if (t1 > 8) t1 = 8;
                int s0 = tL < t0 ? tL : t0; if (t1 < s0) s0 = t1;
                int s2 = tL > t0 ? tL : t0; if (t1 > s2) s2 = t1;
                const int s1 = tL + t0 + t1 - s0 - s2;
                float* v = L.e[(rL * 23 + r0) * 2 + e].v;
                v[0] = (tL <= s0) ? 1.0f : 0.0f;
                v[1] = (t0 <= s0) ? 1.0f : 0.0f;
                v[2] = (t1 <= s0) ? 1.0f : 0.0f;
                v[3] = (float)(s1 - s0);
                v[4] = (tL <= s1) ? 1.0f : 0.0f;
                v[5] = (t0 <= s1) ? 1.0f : 0.0f;
                v[6] = (t1 <= s1) ? 1.0f : 0.0f;
                v[7] = (float)(s2 - s1);
                v[8]  = (float)s0;
                v[9]  = (float)(8 - s2);
                v[10] = 0.0f;
                v[11] = 0.0f;
            }
    return L;
}

__device__ constexpr LutAll d_lut = gen_lut();

__global__ void __launch_bounds__(256)
costvol3d_kernel(const float* __restrict__ fl,
                 const float* __restrict__ fr,
                 const float* __restrict__ wf,
                 float* __restrict__ out)
{
    const int t  = blockIdx.x * blockDim.x + threadIdx.x;
    const int q0 = t * 4;
    if (q0 >= TOTAL) return;

    const unsigned LASTF = (unsigned)(NF - 1);
    const unsigned LASTW = (unsigned)(NW - 1);

    // Quad-invariant coordinates (quads never cross a row or batch slab).
    const int w2   = q0 & (W_ - 1);
    const int base = q0 - w2;
    const int x    = q0 >> 15;
    const int s    = x - 23 * ((x * 179) >> 12);   // x % 23 (x < 184)
    const float shiftf = (float)(s - 11);
    const float w2f    = (float)w2;

    // wflow: quotient crosses at most once inside a quad.
    const unsigned uq = (unsigned)q0;
    const unsigned wq = uq / 23u;
    const int      rq = (int)(uq - wq * 23u);
    const float wA = __ldg(wf + wq);
    const float wB = __ldg(wf + min(wq + 1u, LASTW));
    const float dispA = wA - shiftf;
    const float dispB = wB - shiftf;

    // L stream: quotients over the quad span iL..iL+2 (+1 for crossing).
    const unsigned pL  = uq * 8u;
    const unsigned iL  = pL / 23u;
    const int      rL0 = (int)(pL - iL * 23u);
    const float F0 = __ldg(fl + iL);
    const float F1 = __ldg(fl + min(iL + 1u, LASTF));
    const float F2 = __ldg(fl + min(iL + 2u, LASTF));
    const float F3 = __ldg(fl + min(iL + 3u, LASTF));

    float res[4];
#pragma unroll
    for (int k = 0; k < 4; k++) {
        const float disp = (rq + k < 23) ? dispA : dispB;

        // L-stream phase/values via compares (no per-k division)
        const int  off = rL0 + 8 * k;                 // <= 46
        const bool j1  = (off >= 23);
        const bool j2  = (off >= 46);
        const int  rL  = off - (j1 ? 23 : 0) - (j2 ? 23 : 0);
        const float A0 = j2 ? F2 : (j1 ? F1 : F0);
        const float A1 = j2 ? F3 : (j1 ? F2 : F1);

        // Bilinear coords — bit-identical to reference fp sequence
        const float xq   = (w2f + (float)k) - disp;
        const float x0f  = floorf(xq);
        const float frac = xq - x0f;
        int x0i = (int)x0f;
        x0i = min(max(x0i, 0), W_ - 1);

        // One division; second tap derived (p1 - p0 is 0 or 8).
        const unsigned p0 = (unsigned)(base + x0i) * 8u;
        const unsigned i0 = p0 / 23u;
        const int      r0 = (int)(p0 - i0 * 23u);
        const bool e   = (x0i < W_ - 1);
        const bool inc = e && (r0 >= 15);             // i1 == i0 + 1 ?

        // i1 in {i0, i0+1} -> 3 loads cover both warp taps.
        const float B0 = __ldg(fr + i0);
        const float B1 = __ldg(fr + min(i0 + 1u, LASTF));
        const float B2 = __ldg(fr + min(i0 + 2u, LASTF));
        const float C0 = inc ? B1 : B0;
        const float C1 = inc ? B2 : B1;

        // Segment structure from compile-time LUT.
        const int idx = (rL * 23 + r0) * 2 + (e ? 1 : 0);
        const float4* lp = reinterpret_cast<const float4*>(d_lut.e[idx].v);
        const float4 g1 = __ldg(lp);
        const float4 g2 = __ldg(lp + 1);
        const float4 g3 = __ldg(lp + 2);

        // e_c = L_c - (v0_c + frac*(v1_c - v0_c)); deltas on each flip:
        const float dA = A1 - A0;                 // L flip
        const float D0 = (frac - 1.0f) * (B1 - B0);   // v0 flip
        const float D1 = -frac * (C1 - C0);           // v1 flip
        const float e0 = fmaf(-frac, C0 - B0, A0 - B0);
        const float e1 = fmaf(g1.x, dA, fmaf(g1.y, D0, fmaf(g1.z, D1, e0)));
        const float e2 = fmaf(g2.x, dA, fmaf(g2.y, D0, fmaf(g2.z, D1, e0)));
        const float e3 = e0 + (dA + (D0 + D1));

        float acc = g3.x * fabsf(e0);
        acc = fmaf(g1.w, fabsf(e1), acc);
        acc = fmaf(g2.w, fabsf(e2), acc);
        acc = fmaf(g3.y, fabsf(e3), acc);
        res[k] = acc;
    }

    *reinterpret_cast<float4*>(out + q0) =
        make_float4(res[0], res[1], res[2], res[3]);
}

extern "C" void kernel_launch(void* const* d_in, const int* in_sizes, int n_in,
                              void* d_out, int out_size)
{
    const float* feat_l = (const float*)d_in[0];
    const float* feat_r = (const float*)d_in[1];
    const float* wflow  = (const float*)d_in[2];
    float* out = (float*)d_out;

    const int threads = 256;
    const int quads   = TOTAL / 4;                       // 1,507,328
    const int blocks  = (quads + threads - 1) / threads; // 5888
    costvol3d_kernel<<<blocks, threads>>>(feat_l, feat_r, wflow, out);
}

// round 12
// speedup vs baseline: 2.2845x; 2.2845x over previous
#include <cuda_runtime.h>

// CostVolume3D: B=8, H=128, W=256, C=8, D=23.
// Group-serial: thread handles the 23 outputs sharing wflow[m] (m = q/23).
// Within a group disp/frac are constant, the L-stream and warp-tap streams
// advance by fixed numerator step 8 (mod 23) -> rolling 2-/3-element windows,
// ONE integer division per group. Segment-sum via sort of 3 (t, delta) pairs.
// Rare row-crossing re-inits tap state. Stores staged through smem (stride-23
// STS is bank-conflict-free), streamed out as coalesced float4.

#define W_ 256
#define D_ 23
static constexpr int TOTAL = 8 * 128 * 256 * 23;   // 6,029,312
static constexpr int NF    = 8 * 128 * 256 * 8;    // 2,097,152
static constexpr int NW    = 8 * 128 * 256;        // 262,144 groups
static constexpr int TPB   = 128;                  // 1 group / thread

__global__ void __launch_bounds__(TPB)
costvol3d_kernel(const float* __restrict__ fl,
                 const float* __restrict__ fr,
                 const float* __restrict__ wf,
                 float* __restrict__ out)
{
    __shared__ float sbuf[TPB * D_];
    const int tid = threadIdx.x;
    const int m   = blockIdx.x * TPB + tid;        // < NW exactly (2048*128)
    const unsigned LASTF = (unsigned)(NF - 1);

    const int q0 = m * 23;
    const float w = __ldg(wf + m);

    // position state
    int w2v  = q0 & (W_ - 1);
    int base = q0 - w2v;
    int x    = q0 >> 15;
    int s    = x - 23 * ((x * 179) >> 12);         // x % 23 (x < 184)

    // L-stream rolling state: pL = 8*q0 = 184m -> iA = 8m, rL = 0.
    // Continuous across row crossings.
    int   iA  = m * 8;
    float rLf = 0.0f;
    float A0  = __ldg(fl + iA);
    float A1  = __ldg(fl + iA + 1);                // 8m+1 <= LASTF always

    // tap state (re-initialized at row crossings)
    float disp, frac, fm1, r0f, W0, W1, W2;
    int   x0v, iW;
    {
        disp = w - (float)(s - 11);
        const float xq  = (float)w2v - disp;
        const float x0f = floorf(xq);
        frac = xq - x0f;
        fm1  = frac - 1.0f;
        x0v  = (int)x0f;
        const int x0i = min(max(x0v, 0), W_ - 1);
        const unsigned p0 = (unsigned)(base + x0i) * 8u;
        const unsigned i0 = p0 / 23u;
        r0f = (float)(int)(p0 - i0 * 23u);
        iW  = (int)i0;
        W0 = __ldg(fr + iW);
        W1 = __ldg(fr + min((unsigned)iW + 1u, LASTF));
        W2 = __ldg(fr + min((unsigned)iW + 2u, LASTF));
    }

    float* sb = sbuf + tid * D_;

#pragma unroll 1
    for (int j = 0; j < D_; j++) {
        if (w2v == W_) {                           // rare: row crossing
            w2v = 0; base += W_;
            if ((base & 32767) == 0) s = (s == 22) ? 0 : s + 1;  // x++
            disp = w - (float)(s - 11);
            const float xq  = -disp;               // w2 = 0
            const float x0f = floorf(xq);
            frac = xq - x0f;
            fm1  = frac - 1.0f;
            x0v  = (int)x0f;
            const int x0i = min(max(x0v, 0), W_ - 1);
            const unsigned p0 = (unsigned)(base + x0i) * 8u;
            const unsigned i0 = p0 / 23u;
            r0f = (float)(int)(p0 - i0 * 23u);
            iW  = (int)i0;
            W0 = __ldg(fr + iW);
            W1 = __ldg(fr + min((unsigned)iW + 1u, LASTF));
            W2 = __ldg(fr + min((unsigned)iW + 2u, LASTF));
        }

        // ---- output j ----
        const bool  e    = (x0v < W_ - 1);         // x1i distinct from x0i?
        const bool  hi0  = (r0f >= 15.0f);
        const float nr0  = hi0 ? (r0f - 15.0f) : (r0f + 8.0f);  // (r0+8)%23
        const float r1f  = e ? nr0 : r0f;
        const bool  inc  = e && hi0;               // i1 == i0 + 1 ?
        const float C0   = inc ? W1 : W0;
        const float C1   = inc ? W2 : W1;

        // flip points (stream uses pre-flip value for c < t)
        const float tL = fminf(23.0f - rLf, 8.0f);
        const float t0 = fminf(23.0f - r0f, 8.0f);
        const float t1 = fminf(23.0f - r1f, 8.0f);

        // e_c = A - (1-frac)B - frac*C ; deltas applied at each flip
        const float dA = A1 - A0;
        const float D0 = fm1 * (W1 - W0);
        const float D1 = -frac * (C1 - C0);
        const float e0 = fmaf(-frac, C0 - W0, A0 - W0);

        // sort the 3 (t, delta) pairs ascending by t (ties: zero-length segs)
        float ka = tL, da = dA, kb = t0, db = D0, kc = t1, dc = D1;
        { const bool p = kb <= kc;
          const float kl = p ? kb : kc, kh = p ? kc : kb;
          const float dl = p ? db : dc, dh = p ? dc : db;
          kb = kl; db = dl; kc = kh; dc = dh; }
        { const bool p = ka <= kb;
          const float kl = p ? ka : kb, kh = p ? kb : ka;
          const float dl = p ? da : db, dh = p ? db : da;
          ka = kl; da = dl; kb = kh; db = dh; }
        { const bool p = kb <= kc;
          const float kl = p ? kb : kc, kh = p ? kc : kb;
          const float dl = p ? db : dc, dh = p ? dc : db;
          kb = kl; db = dl; kc = kh; dc = dh; }

        const float e1 = e0 + da;
        const float e2 = e1 + db;
        const float e3 = e2 + dc;

        float acc = ka * fabsf(e0);
        acc = fmaf(kb - ka,   fabsf(e1), acc);
        acc = fmaf(kc - kb,   fabsf(e2), acc);
        acc = fmaf(8.0f - kc, fabsf(e3), acc);
        sb[j] = acc;                               // stride-23: conflict-free

        // ---- advance streams ----
        const bool advL = (rLf >= 15.0f);
        rLf = advL ? (rLf - 15.0f) : (rLf + 8.0f);
        if (advL) {
            iA += 1;
            A0 = A1;
            A1 = __ldg(fl + min((unsigned)iA + 1u, LASTF));
        }
        x0v += 1;
        if (x0v >= 1 && x0v <= W_ - 1) {           // tap pixel actually moved
            r0f = nr0;
            if (hi0) {
                iW += 1;
                W0 = W1; W1 = W2;
                W2 = __ldg(fr + min((unsigned)iW + 2u, LASTF));
            }
        }
        w2v += 1;
    }

    __syncthreads();

    // coalesced writeout: block owns out[blockIdx.x*2944 .. +2944), 16B-aligned
    const float4* s4 = reinterpret_cast<const float4*>(sbuf);
    float4* o4 = reinterpret_cast<float4*>(out + blockIdx.x * (TPB * D_));
    constexpr int NV4 = TPB * D_ / 4;              // 736
#pragma unroll
    for (int i = 0; i < (NV4 + TPB - 1) / TPB; i++) {
        const int idx = i * TPB + tid;
        if (idx < NV4) o4[idx] = s4[idx];
    }
}

extern "C" void kernel_launch(void* const* d_in, const int* in_sizes, int n_in,
                              void* d_out, int out_size)
{
    const float* feat_l = (const float*)d_in[0];
    const float* feat_r = (const float*)d_in[1];
    const float* wflow  = (const float*)d_in[2];
    float* out = (float*)d_out;

    const int blocks = NW / TPB;                   // 2048
    costvol3d_kernel<<<blocks, TPB>>>(feat_l, feat_r, wflow, out);
}

// round 14
// speedup vs baseline: 2.7757x; 1.2151x over previous
#include <cuda_runtime.h>

// CostVolume3D: B=8, H=128, W=256, C=8, D=23.
// Group-serial (thread owns the 23 outputs of wflow[m]) with the 23-iter loop
// FULLY UNROLLED: rL_j = (8j)%23 starts at 0 for every group, so the L-stream
// phase tL_j, the L-window advance schedule, and its load addresses are all
// compile-time. tL==8 on 16/23 iterations -> no L-flip, 3-segment sum.
// Tap segment order resolved by closed form on hi0 (no sort).
// Rare row-crossing reinit; stores staged via stride-23 smem, float4 out.

#define W_ 256
#define D_ 23
static constexpr int NF  = 8 * 128 * 256 * 8;    // 2,097,152
static constexpr int NW  = 8 * 128 * 256;        // 262,144 groups
static constexpr int TPB = 128;
static constexpr unsigned LASTF = (unsigned)(NF - 1);

static __device__ __forceinline__ void tap_init(
    const float* __restrict__ fr, float w, int s, int w2v, int base,
    float& frac, float& fm1, float& r0f, int& x0v, int& iW,
    float& W0, float& W1, float& W2)
{
    const float disp = w - (float)(s - 11);
    const float xq   = (float)w2v - disp;
    const float x0f  = floorf(xq);
    frac = xq - x0f;
    fm1  = frac - 1.0f;
    x0v  = (int)x0f;
    const int x0i = min(max(x0v, 0), W_ - 1);
    const unsigned p0 = (unsigned)(base + x0i) * 8u;
    const unsigned i0 = p0 / 23u;
    r0f = (float)(int)(p0 - i0 * 23u);
    iW  = (int)i0;
    W0 = __ldg(fr + iW);
    W1 = __ldg(fr + min((unsigned)iW + 1u, LASTF));
    W2 = __ldg(fr + min((unsigned)iW + 2u, LASTF));
}

__global__ void __launch_bounds__(TPB)
costvol3d_kernel(const float* __restrict__ fl,
                 const float* __restrict__ fr,
                 const float* __restrict__ wf,
                 float* __restrict__ out)
{
    __shared__ float sbuf[TPB * D_];
    const int tid = threadIdx.x;
    const int m   = blockIdx.x * TPB + tid;        // exactly NW threads

    const int q0 = m * 23;
    const float w = __ldg(wf + m);

    int w2v  = q0 & (W_ - 1);
    int base = q0 - w2v;
    const int x = q0 >> 15;
    int s = x - 23 * ((x * 179) >> 12);            // x % 23 (x < 184)

    // L stream: pL = 184m -> index 8m, remainder 0 (compile-time schedule).
    const int iA = m * 8;
    float A0 = __ldg(fl + iA);
    float A1 = __ldg(fl + iA + 1);                 // 8m+1 <= NF-7 always
    float dA = A1 - A0;

    float frac, fm1, r0f, W0, W1, W2;
    int   x0v, iW;
    tap_init(fr, w, s, w2v, base, frac, fm1, r0f, x0v, iW, W0, W1, W2);

    float* sb = sbuf + tid * D_;

    // rL_j = (8j) % 23 ; tL_j = min(23 - rL_j, 8)
    constexpr float TLC[23] = {8,8,7,8,8,6,8,8,5,8,8,4,8,8,3,8,8,2,8,8,1,8,8};
    // advance L window after j (rL_j >= 15, j=22 advance unused -> skipped);
    // ANEXT = compile-time A1 load offset from iA for that advance.
    constexpr bool ADV[23] = {0,0,1,0,0,1,0,0,1,0,0,1,0,0,1,0,0,1,0,0,1,0,0};
    constexpr int  ANEXT[23] = {0,0,2,0,0,3,0,0,4,0,0,5,0,0,6,0,0,7,0,0,8,0,0};

#pragma unroll
    for (int j = 0; j < D_; j++) {
        if (w2v == W_) {                           // rare: row crossing
            w2v = 0; base += W_;
            if ((base & 32767) == 0) s = (s == 22) ? 0 : s + 1;
            tap_init(fr, w, s, 0, base, frac, fm1, r0f, x0v, iW, W0, W1, W2);
        }

        const bool  e    = (x0v < W_ - 1);         // taps distinct?
        const bool  hi0  = (r0f >= 15.0f);
        const float t23  = 23.0f - r0f;
        // sorted tap flip points u <= v and matching deltas (closed form)
        const float u = hi0 ? t23 : (e ? fminf(15.0f - r0f, 8.0f) : 8.0f);
        const float v = (!e && hi0) ? t23 : 8.0f;

        const float dW01 = W1 - W0;
        const float dW12 = W2 - W1;
        const bool  inc  = e && hi0;               // i1 == i0 + 1 ?
        const float D0 = fm1 * dW01;
        const float D1 = -frac * (inc ? dW12 : dW01);
        const float du = hi0 ? D0 : D1;
        const float dv = hi0 ? D1 : D0;
        const float be = A0 - W0;
        const float e0 = inc ? fmaf(-frac, dW01, be) : be;

        float acc;
        if (TLC[j] >= 8.0f) {
            // no L-flip inside c=0..7: 3 segments, dA unused
            const float g1 = e0 + du;
            const float g2 = g1 + dv;
            acc = u * fabsf(e0);
            acc = fmaf(v - u,    fabsf(g1), acc);
            acc = fmaf(8.0f - v, fabsf(g2), acc);
        } else {
            const float tLc = TLC[j];              // immediate
            const float a = fminf(tLc, u);
            const float c = fmaxf(tLc, v);
            const float b = ((tLc + u) + v) - (a + c);
            const float g3 = e0 + (dA + (du + dv));
            const float g1 = e0 + ((u <= tLc) ? du : dA);
            const float g2 = g3 - ((v <= tLc) ? dA : dv);
            acc = a * fabsf(e0);
            acc = fmaf(b - a,    fabsf(g1), acc);
            acc = fmaf(c - b,    fabsf(g2), acc);
            acc = fmaf(8.0f - c, fabsf(g3), acc);
        }
        sb[j] = acc;                               // stride-23: conflict-free

        // ---- advance tap stream ----
        const float nr0 = hi0 ? (r0f - 15.0f) : (r0f + 8.0f);  // (r0+8)%23
        x0v += 1;
        if ((unsigned)(x0v - 1) < (unsigned)(W_ - 1)) {  // pixel moved
            r0f = nr0;
            if (hi0) {
                iW += 1;
                W0 = W1; W1 = W2;
                W2 = __ldg(fr + min((unsigned)iW + 2u, LASTF));
            }
        }
        w2v += 1;

        // ---- advance L window (compile-time schedule) ----
        if (ADV[j]) {
            A0 = A1;
            A1 = __ldg(fl + min((unsigned)(iA + ANEXT[j]), LASTF));
            dA = A1 - A0;
        }
    }

    __syncthreads();

    // coalesced writeout: block owns out[blockIdx.x*2944 .. +2944)
    const float4* s4 = reinterpret_cast<const float4*>(sbuf);
    float4* o4 = reinterpret_cast<float4*>(out + blockIdx.x * (TPB * D_));
    constexpr int NV4 = TPB * D_ / 4;              // 736
#pragma unroll
    for (int i = 0; i < (NV4 + TPB - 1) / TPB; i++) {
        const int idx = i * TPB + tid;
        if (idx < NV4) o4[idx] = s4[idx];
    }
}

extern "C" void kernel_launch(void* const* d_in, const int* in_sizes, int n_in,
                              void* d_out, int out_size)
{
    const float* feat_l = (const float*)d_in[0];
    const float* feat_r = (const float*)d_in[1];
    const float* wflow  = (const float*)d_in[2];
    float* out = (float*)d_out;

    costvol3d_kernel<<<NW / TPB, TPB>>>(feat_l, feat_r, wflow, out);
}